// round 12
// baseline (speedup 1.0000x reference)
#include <cuda_runtime.h>
#include <cuda_fp16.h>
#include <cstdint>

#define N_TOK 8192
#define DIM   2048
#define NEXP  8

#define BM 128
#define BN 128
#define BK 64                  // fp16 K elems per chunk (128B row)
#define NCH (DIM / BK)         // 32
#define NSTAGE 3

#define PITCH 144              // 128B data + 16B pad -> conflict-free LDSM
#define A_TILE (BM * PITCH)    // 18432
#define B_TILE (BN * PITCH)    // 18432
#define ST_SIZE (A_TILE + B_TILE)        // 36864
#define OFF_TOK  (NSTAGE * ST_SIZE)      // 110592
#define OFF_WT   (OFF_TOK + 512)
#define OFF_SLOT (OFF_WT + 512)
#define SMEM_BYTES (OFF_SLOT + 512)      // 112128

#define GATE_BLOCKS 512
#define CONV_N4 ((size_t)NEXP * DIM * DIM / 4)
#define CONV_BLOCKS ((int)(CONV_N4 / 256))
#define PREP_BLOCKS (GATE_BLOCKS + CONV_BLOCKS)

// ---- scratch ---------------------------------------------------------------
__device__ int   g_count[NEXP];
__device__ int   g_tok[NEXP][N_TOK];
__device__ float g_wt[NEXP][N_TOK];
__device__ int   g_slot[NEXP][N_TOK];
__device__ float g_C[2ull * N_TOK * DIM];
__device__ __align__(16) __half g_Wh[(size_t)NEXP * DIM * DIM];
__device__ __align__(16) __half g_Xh[(size_t)N_TOK * DIM];

// ---- helpers -----------------------------------------------------------------
__device__ __forceinline__ uint32_t smem_u32(const void* p) {
    return (uint32_t)__cvta_generic_to_shared(p);
}
__device__ __forceinline__ void cp16(uint32_t dst, const void* src) {
    asm volatile("cp.async.cg.shared.global [%0], [%1], 16;" :: "r"(dst), "l"(src));
}
__device__ __forceinline__ void cp_commit() {
    asm volatile("cp.async.commit_group;" ::: "memory");
}
template <int N>
__device__ __forceinline__ void cp_wait() {
    asm volatile("cp.async.wait_group %0;" :: "n"(N) : "memory");
}
__device__ __forceinline__ void ldsm4(uint32_t& r0, uint32_t& r1, uint32_t& r2,
                                      uint32_t& r3, uint32_t addr) {
    asm volatile("ldmatrix.sync.aligned.m8n8.x4.shared.b16 {%0,%1,%2,%3}, [%4];"
                 : "=r"(r0), "=r"(r1), "=r"(r2), "=r"(r3) : "r"(addr));
}
// fp16-accumulator mma: D(fp16x2 x2) = A*B + D  -- 2x rate vs fp32 acc
__device__ __forceinline__ void mma16816_h(uint32_t* d, const uint32_t* a, const uint32_t* b) {
    asm volatile(
        "mma.sync.aligned.m16n8k16.row.col.f16.f16.f16.f16 "
        "{%0,%1}, {%2,%3,%4,%5}, {%6,%7}, {%0,%1};"
        : "+r"(d[0]), "+r"(d[1])
        : "r"(a[0]), "r"(a[1]), "r"(a[2]), "r"(a[3]), "r"(b[0]), "r"(b[1]));
}

// ---- reset -----------------------------------------------------------------
__global__ void reset_kernel() {
    if (threadIdx.x < NEXP) g_count[threadIdx.x] = 0;
}

// ---- prep: gating (blocks 0..511) + W fp32->fp16 convert (rest) ----------------
__global__ void prep_kernel(const float* __restrict__ x,
                            const float* __restrict__ Wg,
                            const float* __restrict__ bg,
                            const float* __restrict__ We) {
    if (blockIdx.x >= GATE_BLOCKS) {
        size_t i = (size_t)(blockIdx.x - GATE_BLOCKS) * blockDim.x + threadIdx.x;
        if (i < CONV_N4) {
            float4 v = __ldg(((const float4*)We) + i);
            __half2 a = __floats2half2_rn(v.x, v.y);
            __half2 b = __floats2half2_rn(v.z, v.w);
            ((uint2*)g_Wh)[i] = make_uint2(*(uint32_t*)&a, *(uint32_t*)&b);
        }
        return;
    }

    int warp = (blockIdx.x * blockDim.x + threadIdx.x) >> 5;
    int lane = threadIdx.x & 31;
    int t0 = warp * 2;
    if (t0 >= N_TOK) return;

    const float4* xr0 = reinterpret_cast<const float4*>(x + (size_t)t0 * DIM);
    const float4* xr1 = reinterpret_cast<const float4*>(x + (size_t)(t0 + 1) * DIM);
    uint2* xh0 = reinterpret_cast<uint2*>(g_Xh + (size_t)t0 * DIM);
    uint2* xh1 = reinterpret_cast<uint2*>(g_Xh + (size_t)(t0 + 1) * DIM);

    float acc0[NEXP], acc1[NEXP];
#pragma unroll
    for (int e = 0; e < NEXP; e++) { acc0[e] = 0.f; acc1[e] = 0.f; }

    for (int d4 = lane; d4 < DIM / 4; d4 += 32) {
        float4 xv0 = __ldg(&xr0[d4]);
        float4 xv1 = __ldg(&xr1[d4]);
        {
            __half2 a0 = __floats2half2_rn(xv0.x, xv0.y);
            __half2 b0 = __floats2half2_rn(xv0.z, xv0.w);
            xh0[d4] = make_uint2(*(uint32_t*)&a0, *(uint32_t*)&b0);
            __half2 a1 = __floats2half2_rn(xv1.x, xv1.y);
            __half2 b1 = __floats2half2_rn(xv1.z, xv1.w);
            xh1[d4] = make_uint2(*(uint32_t*)&a1, *(uint32_t*)&b1);
        }
#pragma unroll
        for (int e = 0; e < NEXP; e++) {
            float4 wv = __ldg(&reinterpret_cast<const float4*>(Wg + (size_t)e * DIM)[d4]);
            acc0[e] += xv0.x * wv.x + xv0.y * wv.y + xv0.z * wv.z + xv0.w * wv.w;
            acc1[e] += xv1.x * wv.x + xv1.y * wv.y + xv1.z * wv.z + xv1.w * wv.w;
        }
    }
#pragma unroll
    for (int e = 0; e < NEXP; e++) {
#pragma unroll
        for (int off = 16; off > 0; off >>= 1) {
            acc0[e] += __shfl_xor_sync(0xffffffffu, acc0[e], off);
            acc1[e] += __shfl_xor_sync(0xffffffffu, acc1[e], off);
        }
    }

    if (lane == 0) {
#pragma unroll
        for (int t = 0; t < 2; t++) {
            float* acc = t ? acc1 : acc0;
            int tok = t0 + t;
            float lg[NEXP];
            float mx = -1e30f;
#pragma unroll
            for (int e = 0; e < NEXP; e++) { lg[e] = acc[e] + bg[e]; mx = fmaxf(mx, lg[e]); }
            float s = 0.f;
#pragma unroll
            for (int e = 0; e < NEXP; e++) { lg[e] = expf(lg[e] - mx); s += lg[e]; }
            float inv = 1.f / s;

            int e0 = 0;
#pragma unroll
            for (int e = 1; e < NEXP; e++) if (lg[e] > lg[e0]) e0 = e;
            int e1 = (e0 == 0) ? 1 : 0;
#pragma unroll
            for (int e = 0; e < NEXP; e++) if (e != e0 && lg[e] > lg[e1]) e1 = e;

            int p0 = atomicAdd(&g_count[e0], 1);
            g_tok[e0][p0] = tok; g_wt[e0][p0] = lg[e0] * inv; g_slot[e0][p0] = 0;
            int p1 = atomicAdd(&g_count[e1], 1);
            g_tok[e1][p1] = tok; g_wt[e1][p1] = lg[e1] * inv; g_slot[e1][p1] = 1;
        }
    }
}

// ---- fp16-acc mma expert GEMM ---------------------------------------------------
// CTA 128x128, 512 thr, warp tile 32x32 (4m x 4n). fp16 accumulation chained over
// one K=64 chunk (4 mmas), flushed to fp32 master once per chunk.
__global__ __launch_bounds__(512, 1)
void expert_gemm_mma(const float* __restrict__ be) {
    extern __shared__ __align__(128) char smem[];

    const int e  = blockIdx.z;
    const int Me = g_count[e];
    const int m0 = blockIdx.y * BM;
    if (m0 >= Me) return;
    const int n0 = blockIdx.x * BN;

    const int tid  = threadIdx.x;
    const int wid  = tid >> 5;
    const int lane = tid & 31;

    int*   tok_s  = (int*)(smem + OFF_TOK);
    float* w_s    = (float*)(smem + OFF_WT);
    int*   slot_s = (int*)(smem + OFF_SLOT);

    if (tid < BM) {
        int gm = m0 + tid;
        if (gm < Me) {
            tok_s[tid] = g_tok[e][gm]; w_s[tid] = g_wt[e][gm]; slot_s[tid] = g_slot[e][gm];
        } else {
            tok_s[tid] = 0; w_s[tid] = 0.f; slot_s[tid] = 0;
        }
    }
    __syncthreads();

    // loader: 4 threads per row, each does 2 contiguous 16B chunks (32B)
    const int lr = tid >> 2;            // 0..127
    const int lc = tid & 3;             // 32B segment
    const __half* Asrc = g_Xh + (size_t)tok_s[lr] * DIM + lc * 16;
    const __half* Bsrc = g_Wh + (size_t)e * DIM * DIM + (size_t)(n0 + lr) * DIM + lc * 16;

    const uint32_t sbase = smem_u32(smem);
    const uint32_t a_dst = sbase + lr * PITCH + lc * 32;
    const uint32_t b_dst = sbase + A_TILE + lr * PITCH + lc * 32;

    // 16 warps: 4m x 4n, warp tile 32x32
    const int wm = (wid & 3) * 32;
    const int wn = (wid >> 2) * 32;

    float macc[2][4][4];
#pragma unroll
    for (int mf = 0; mf < 2; mf++)
#pragma unroll
        for (int nf = 0; nf < 4; nf++)
#pragma unroll
            for (int j = 0; j < 4; j++) macc[mf][nf][j] = 0.f;

    const uint32_t aRowAddr = (uint32_t)((wm + (lane & 15)) * PITCH + (lane >> 4) * 16);
    const uint32_t bRowAddr = (uint32_t)((wn + (lane & 7) + ((lane >> 4) << 3)) * PITCH +
                                         ((lane >> 3) & 1) * 16);

    // prologue: chunks 0,1 into stages 0,1
#pragma unroll
    for (int c = 0; c < 2; c++) {
        const uint32_t so = c * ST_SIZE;
        const int k0 = c * BK;
        cp16(a_dst + so,      Asrc + k0);
        cp16(a_dst + so + 16, Asrc + k0 + 8);
        cp16(b_dst + so,      Bsrc + k0);
        cp16(b_dst + so + 16, Bsrc + k0 + 8);
        cp_commit();
    }

    int st = 0;
    for (int c = 0; c < NCH; c++) {
        cp_wait<1>();              // chunk c resident
        __syncthreads();           // stage (c-1)%3 retired by all warps

        const uint32_t bA = sbase + st * ST_SIZE;
        const uint32_t bB = bA + A_TILE;

        // fp16 chunk accumulators (chain over 4 ks-steps)
        uint32_t hacc[2][4][2];
#pragma unroll
        for (int mf = 0; mf < 2; mf++)
#pragma unroll
            for (int nf = 0; nf < 4; nf++) { hacc[mf][nf][0] = 0u; hacc[mf][nf][1] = 0u; }

#pragma unroll
        for (int ks = 0; ks < 4; ks++) {
            const uint32_t kb = ks * 32;
            uint32_t ah[2][4], bb[4][2];
#pragma unroll
            for (int mf = 0; mf < 2; mf++)
                ldsm4(ah[mf][0], ah[mf][1], ah[mf][2], ah[mf][3],
                      bA + aRowAddr + mf * 16 * PITCH + kb);
#pragma unroll
            for (int q = 0; q < 2; q++)
                ldsm4(bb[2 * q][0], bb[2 * q][1], bb[2 * q + 1][0], bb[2 * q + 1][1],
                      bB + bRowAddr + q * 16 * PITCH + kb);
#pragma unroll
            for (int mf = 0; mf < 2; mf++)
#pragma unroll
                for (int nf = 0; nf < 4; nf++)
                    mma16816_h(hacc[mf][nf], ah[mf], bb[nf]);
        }

        // flush fp16 chunk sum into fp32 master
#pragma unroll
        for (int mf = 0; mf < 2; mf++)
#pragma unroll
            for (int nf = 0; nf < 4; nf++) {
                float2 f0 = __half22float2(*(__half2*)&hacc[mf][nf][0]);
                float2 f1 = __half22float2(*(__half2*)&hacc[mf][nf][1]);
                macc[mf][nf][0] += f0.x;
                macc[mf][nf][1] += f0.y;
                macc[mf][nf][2] += f1.x;
                macc[mf][nf][3] += f1.y;
            }

        // issue chunk c+2 into stage (c+2)%3 == (c-1)%3
        if (c + 2 < NCH) {
            const uint32_t so = ((c + 2) % NSTAGE) * ST_SIZE;
            const int k0 = (c + 2) * BK;
            cp16(a_dst + so,      Asrc + k0);
            cp16(a_dst + so + 16, Asrc + k0 + 8);
            cp16(b_dst + so,      Bsrc + k0);
            cp16(b_dst + so + 16, Bsrc + k0 + 8);
        }
        cp_commit();

        st = (st + 1 == NSTAGE) ? 0 : st + 1;
    }

    // ---- epilogue: bias + relu + gate weight -> g_C (coalesced STG) --------------
#pragma unroll
    for (int mf = 0; mf < 2; mf++) {
        const int lm0 = wm + mf * 16 + (lane >> 2);
        const int lm1 = lm0 + 8;
        const bool ok0 = (m0 + lm0) < Me;
        const bool ok1 = (m0 + lm1) < Me;
        const float w0 = w_s[lm0], w1 = w_s[lm1];
        float* d0 = g_C + (size_t)slot_s[lm0] * N_TOK * DIM + (size_t)tok_s[lm0] * DIM;
        float* d1 = g_C + (size_t)slot_s[lm1] * N_TOK * DIM + (size_t)tok_s[lm1] * DIM;
#pragma unroll
        for (int nf = 0; nf < 4; nf++) {
            const int col = n0 + wn + nf * 8 + (lane & 3) * 2;
            const float b0 = __ldg(&be[(size_t)e * DIM + col]);
            const float b1 = __ldg(&be[(size_t)e * DIM + col + 1]);
            if (ok0) {
                float v0 = fmaxf(macc[mf][nf][0] + b0, 0.f) * w0;
                float v1 = fmaxf(macc[mf][nf][1] + b1, 0.f) * w0;
                *(float2*)(d0 + col) = make_float2(v0, v1);
            }
            if (ok1) {
                float v2 = fmaxf(macc[mf][nf][2] + b0, 0.f) * w1;
                float v3 = fmaxf(macc[mf][nf][3] + b1, 0.f) * w1;
                *(float2*)(d1 + col) = make_float2(v2, v3);
            }
        }
    }
}

// ---- combine -------------------------------------------------------------------
__global__ void combine_kernel(float* __restrict__ out) {
    size_t i = (size_t)blockIdx.x * blockDim.x + threadIdx.x;
    const float4* c0 = (const float4*)g_C;
    const float4* c1 = (const float4*)(g_C + (size_t)N_TOK * DIM);
    if (i < (size_t)N_TOK * DIM / 4) {
        float4 a = c0[i];
        float4 b = c1[i];
        ((float4*)out)[i] = make_float4(a.x + b.x, a.y + b.y, a.z + b.z, a.w + b.w);
    }
}

// ---- launch ----------------------------------------------------------------------
extern "C" void kernel_launch(void* const* d_in, const int* in_sizes, int n_in,
                              void* d_out, int out_size) {
    const float* x  = (const float*)d_in[0];
    const float* We = (const float*)d_in[1];
    const float* be = (const float*)d_in[2];
    const float* Wg = (const float*)d_in[3];
    const float* bg = (const float*)d_in[4];
    float* out = (float*)d_out;

    cudaFuncSetAttribute(expert_gemm_mma,
                         cudaFuncAttributeMaxDynamicSharedMemorySize, SMEM_BYTES);

    reset_kernel<<<1, 32>>>();
    prep_kernel<<<PREP_BLOCKS, 256>>>(x, Wg, bg, We);
    expert_gemm_mma<<<dim3(DIM / BN, N_TOK / BM, NEXP), 512, SMEM_BYTES>>>(be);
    combine_kernel<<<(N_TOK * DIM / 4) / 256, 256>>>(out);
}

// round 13
// speedup vs baseline: 1.2791x; 1.2791x over previous
#include <cuda_runtime.h>
#include <cuda_fp16.h>
#include <cstdint>

#define N_TOK 8192
#define DIM   2048
#define NEXP  8

#define BM 128
#define BN 256
#define BK 64                  // fp16 K elems per chunk (128B row)
#define NCH (DIM / BK)         // 32
#define NSTAGE 3

#define PITCH 144              // 128B data + 16B pad -> conflict-free LDSM
#define A_TILE (BM * PITCH)    // 18432
#define B_TILE (BN * PITCH)    // 36864
#define ST_SIZE (A_TILE + B_TILE)        // 55296
#define OFF_TOK  (NSTAGE * ST_SIZE)      // 165888
#define OFF_WT   (OFF_TOK + 512)
#define OFF_SLOT (OFF_WT + 512)
#define SMEM_BYTES (OFF_SLOT + 512)      // 167424

#define GATE_BLOCKS 512
#define CONV_N4 ((size_t)NEXP * DIM * DIM / 4)
#define CONV_BLOCKS ((int)(CONV_N4 / 256))
#define PREP_BLOCKS (GATE_BLOCKS + CONV_BLOCKS)

// ---- scratch ---------------------------------------------------------------
__device__ int   g_count[NEXP];
__device__ int   g_tok[NEXP][N_TOK];
__device__ float g_wt[NEXP][N_TOK];
__device__ int   g_slot[NEXP][N_TOK];
__device__ __align__(16) __half g_Ch[2ull * N_TOK * DIM];   // fp16 per-slot scratch
__device__ __align__(16) __half g_Wh[(size_t)NEXP * DIM * DIM];
__device__ __align__(16) __half g_Xh[(size_t)N_TOK * DIM];

// ---- helpers -----------------------------------------------------------------
__device__ __forceinline__ uint32_t smem_u32(const void* p) {
    return (uint32_t)__cvta_generic_to_shared(p);
}
__device__ __forceinline__ void cp16(uint32_t dst, const void* src) {
    asm volatile("cp.async.cg.shared.global [%0], [%1], 16;" :: "r"(dst), "l"(src));
}
__device__ __forceinline__ void cp_commit() {
    asm volatile("cp.async.commit_group;" ::: "memory");
}
template <int N>
__device__ __forceinline__ void cp_wait() {
    asm volatile("cp.async.wait_group %0;" :: "n"(N) : "memory");
}
__device__ __forceinline__ void ldsm4(uint32_t& r0, uint32_t& r1, uint32_t& r2,
                                      uint32_t& r3, uint32_t addr) {
    asm volatile("ldmatrix.sync.aligned.m8n8.x4.shared.b16 {%0,%1,%2,%3}, [%4];"
                 : "=r"(r0), "=r"(r1), "=r"(r2), "=r"(r3) : "r"(addr));
}
__device__ __forceinline__ void mma16816(float* c, const uint32_t* a, const uint32_t* b) {
    asm volatile(
        "mma.sync.aligned.m16n8k16.row.col.f32.f16.f16.f32 "
        "{%0,%1,%2,%3}, {%4,%5,%6,%7}, {%8,%9}, {%0,%1,%2,%3};"
        : "+f"(c[0]), "+f"(c[1]), "+f"(c[2]), "+f"(c[3])
        : "r"(a[0]), "r"(a[1]), "r"(a[2]), "r"(a[3]), "r"(b[0]), "r"(b[1]));
}

// ---- reset -----------------------------------------------------------------
__global__ void reset_kernel() {
    if (threadIdx.x < NEXP) g_count[threadIdx.x] = 0;
}

// ---- prep: gating (blocks 0..511) + W fp32->fp16 convert (rest) ----------------
__global__ void prep_kernel(const float* __restrict__ x,
                            const float* __restrict__ Wg,
                            const float* __restrict__ bg,
                            const float* __restrict__ We) {
    if (blockIdx.x >= GATE_BLOCKS) {
        size_t i = (size_t)(blockIdx.x - GATE_BLOCKS) * blockDim.x + threadIdx.x;
        if (i < CONV_N4) {
            float4 v = __ldg(((const float4*)We) + i);
            __half2 a = __floats2half2_rn(v.x, v.y);
            __half2 b = __floats2half2_rn(v.z, v.w);
            ((uint2*)g_Wh)[i] = make_uint2(*(uint32_t*)&a, *(uint32_t*)&b);
        }
        return;
    }

    int warp = (blockIdx.x * blockDim.x + threadIdx.x) >> 5;
    int lane = threadIdx.x & 31;
    int t0 = warp * 2;
    if (t0 >= N_TOK) return;

    const float4* xr0 = reinterpret_cast<const float4*>(x + (size_t)t0 * DIM);
    const float4* xr1 = reinterpret_cast<const float4*>(x + (size_t)(t0 + 1) * DIM);
    uint2* xh0 = reinterpret_cast<uint2*>(g_Xh + (size_t)t0 * DIM);
    uint2* xh1 = reinterpret_cast<uint2*>(g_Xh + (size_t)(t0 + 1) * DIM);

    float acc0[NEXP], acc1[NEXP];
#pragma unroll
    for (int e = 0; e < NEXP; e++) { acc0[e] = 0.f; acc1[e] = 0.f; }

    for (int d4 = lane; d4 < DIM / 4; d4 += 32) {
        float4 xv0 = __ldg(&xr0[d4]);
        float4 xv1 = __ldg(&xr1[d4]);
        {
            __half2 a0 = __floats2half2_rn(xv0.x, xv0.y);
            __half2 b0 = __floats2half2_rn(xv0.z, xv0.w);
            xh0[d4] = make_uint2(*(uint32_t*)&a0, *(uint32_t*)&b0);
            __half2 a1 = __floats2half2_rn(xv1.x, xv1.y);
            __half2 b1 = __floats2half2_rn(xv1.z, xv1.w);
            xh1[d4] = make_uint2(*(uint32_t*)&a1, *(uint32_t*)&b1);
        }
#pragma unroll
        for (int e = 0; e < NEXP; e++) {
            float4 wv = __ldg(&reinterpret_cast<const float4*>(Wg + (size_t)e * DIM)[d4]);
            acc0[e] += xv0.x * wv.x + xv0.y * wv.y + xv0.z * wv.z + xv0.w * wv.w;
            acc1[e] += xv1.x * wv.x + xv1.y * wv.y + xv1.z * wv.z + xv1.w * wv.w;
        }
    }
#pragma unroll
    for (int e = 0; e < NEXP; e++) {
#pragma unroll
        for (int off = 16; off > 0; off >>= 1) {
            acc0[e] += __shfl_xor_sync(0xffffffffu, acc0[e], off);
            acc1[e] += __shfl_xor_sync(0xffffffffu, acc1[e], off);
        }
    }

    if (lane == 0) {
#pragma unroll
        for (int t = 0; t < 2; t++) {
            float* acc = t ? acc1 : acc0;
            int tok = t0 + t;
            float lg[NEXP];
            float mx = -1e30f;
#pragma unroll
            for (int e = 0; e < NEXP; e++) { lg[e] = acc[e] + bg[e]; mx = fmaxf(mx, lg[e]); }
            float s = 0.f;
#pragma unroll
            for (int e = 0; e < NEXP; e++) { lg[e] = expf(lg[e] - mx); s += lg[e]; }
            float inv = 1.f / s;

            int e0 = 0;
#pragma unroll
            for (int e = 1; e < NEXP; e++) if (lg[e] > lg[e0]) e0 = e;
            int e1 = (e0 == 0) ? 1 : 0;
#pragma unroll
            for (int e = 0; e < NEXP; e++) if (e != e0 && lg[e] > lg[e1]) e1 = e;

            int p0 = atomicAdd(&g_count[e0], 1);
            g_tok[e0][p0] = tok; g_wt[e0][p0] = lg[e0] * inv; g_slot[e0][p0] = 0;
            int p1 = atomicAdd(&g_count[e1], 1);
            g_tok[e1][p1] = tok; g_wt[e1][p1] = lg[e1] * inv; g_slot[e1][p1] = 1;
        }
    }
}

// ---- fp16 mma.sync expert GEMM (R10 config, fp16 scratch epilogue) --------------
__global__ __launch_bounds__(512, 1)
void expert_gemm_mma(const float* __restrict__ be) {
    extern __shared__ __align__(128) char smem[];

    const int e  = blockIdx.z;
    const int Me = g_count[e];
    const int m0 = blockIdx.y * BM;
    if (m0 >= Me) return;
    const int n0 = blockIdx.x * BN;

    const int tid  = threadIdx.x;
    const int wid  = tid >> 5;
    const int lane = tid & 31;

    int*   tok_s  = (int*)(smem + OFF_TOK);
    float* w_s    = (float*)(smem + OFF_WT);
    int*   slot_s = (int*)(smem + OFF_SLOT);

    if (tid < BM) {
        int gm = m0 + tid;
        if (gm < Me) {
            tok_s[tid] = g_tok[e][gm]; w_s[tid] = g_wt[e][gm]; slot_s[tid] = g_slot[e][gm];
        } else {
            tok_s[tid] = 0; w_s[tid] = 0.f; slot_s[tid] = 0;
        }
    }
    __syncthreads();

    const int lr = tid >> 2;        // 0..127
    const int lc = tid & 3;
    const __half* Asrc = g_Xh + (size_t)tok_s[lr] * DIM + lc * 8;
    const __half* Bbase = g_Wh + (size_t)e * DIM * DIM;
    const __half* Bsrc0 = Bbase + (size_t)(n0 + lr) * DIM + lc * 8;
    const __half* Bsrc1 = Bbase + (size_t)(n0 + 128 + lr) * DIM + lc * 8;

    const uint32_t sbase  = smem_u32(smem);
    const uint32_t a_dst  = sbase + lr * PITCH + lc * 16;
    const uint32_t b_dst0 = sbase + A_TILE + lr * PITCH + lc * 16;
    const uint32_t b_dst1 = sbase + A_TILE + (128 + lr) * PITCH + lc * 16;

    const int wm = (wid & 3) * 32;
    const int wn = (wid >> 2) * 64;

    float acc[2][8][4];
#pragma unroll
    for (int mf = 0; mf < 2; mf++)
#pragma unroll
        for (int nf = 0; nf < 8; nf++)
#pragma unroll
            for (int j = 0; j < 4; j++) acc[mf][nf][j] = 0.f;

    const uint32_t aRowAddr = (uint32_t)((wm + (lane & 15)) * PITCH + (lane >> 4) * 16);
    const uint32_t bRowAddr = (uint32_t)((wn + (lane & 7) + ((lane >> 4) << 3)) * PITCH +
                                         ((lane >> 3) & 1) * 16);

    // prologue: chunks 0,1 into stages 0,1
#pragma unroll
    for (int c = 0; c < 2; c++) {
        const uint32_t so = c * ST_SIZE;
        const int k0 = c * BK;
        cp16(a_dst + so,       Asrc + k0);
        cp16(a_dst + so + 64,  Asrc + k0 + 32);
        cp16(b_dst0 + so,      Bsrc0 + k0);
        cp16(b_dst0 + so + 64, Bsrc0 + k0 + 32);
        cp16(b_dst1 + so,      Bsrc1 + k0);
        cp16(b_dst1 + so + 64, Bsrc1 + k0 + 32);
        cp_commit();
    }

    int st = 0;
    for (int c = 0; c < NCH; c++) {
        cp_wait<1>();              // chunk c resident
        __syncthreads();           // stage (c-1)%3 retired by all warps

        const uint32_t bA = sbase + st * ST_SIZE;
        const uint32_t bB = bA + A_TILE;
#pragma unroll
        for (int ks = 0; ks < 4; ks++) {
            const uint32_t kb = ks * 32;
            uint32_t ah[2][4], bb[8][2];
#pragma unroll
            for (int mf = 0; mf < 2; mf++)
                ldsm4(ah[mf][0], ah[mf][1], ah[mf][2], ah[mf][3],
                      bA + aRowAddr + mf * 16 * PITCH + kb);
#pragma unroll
            for (int q = 0; q < 4; q++)
                ldsm4(bb[2 * q][0], bb[2 * q][1], bb[2 * q + 1][0], bb[2 * q + 1][1],
                      bB + bRowAddr + q * 16 * PITCH + kb);
#pragma unroll
            for (int mf = 0; mf < 2; mf++)
#pragma unroll
                for (int nf = 0; nf < 8; nf++)
                    mma16816(acc[mf][nf], ah[mf], bb[nf]);
        }

        // issue chunk c+2 into stage (c+2)%3 == (c-1)%3
        if (c + 2 < NCH) {
            const uint32_t so = ((c + 2) % NSTAGE) * ST_SIZE;
            const int k0 = (c + 2) * BK;
            cp16(a_dst + so,       Asrc + k0);
            cp16(a_dst + so + 64,  Asrc + k0 + 32);
            cp16(b_dst0 + so,      Bsrc0 + k0);
            cp16(b_dst0 + so + 64, Bsrc0 + k0 + 32);
            cp16(b_dst1 + so,      Bsrc1 + k0);
            cp16(b_dst1 + so + 64, Bsrc1 + k0 + 32);
        }
        cp_commit();

        st = (st + 1 == NSTAGE) ? 0 : st + 1;
    }

    // ---- epilogue: bias + relu + gate weight -> g_Ch (fp16, coalesced) -----------
#pragma unroll
    for (int mf = 0; mf < 2; mf++) {
        const int lm0 = wm + mf * 16 + (lane >> 2);
        const int lm1 = lm0 + 8;
        const bool ok0 = (m0 + lm0) < Me;
        const bool ok1 = (m0 + lm1) < Me;
        const float w0 = w_s[lm0], w1 = w_s[lm1];
        __half* d0 = g_Ch + (size_t)slot_s[lm0] * N_TOK * DIM + (size_t)tok_s[lm0] * DIM;
        __half* d1 = g_Ch + (size_t)slot_s[lm1] * N_TOK * DIM + (size_t)tok_s[lm1] * DIM;
#pragma unroll
        for (int nf = 0; nf < 8; nf++) {
            const int col = n0 + wn + nf * 8 + (lane & 3) * 2;
            const float b0 = __ldg(&be[(size_t)e * DIM + col]);
            const float b1 = __ldg(&be[(size_t)e * DIM + col + 1]);
            if (ok0) {
                float v0 = fmaxf(acc[mf][nf][0] + b0, 0.f) * w0;
                float v1 = fmaxf(acc[mf][nf][1] + b1, 0.f) * w0;
                *(__half2*)(d0 + col) = __floats2half2_rn(v0, v1);
            }
            if (ok1) {
                float v2 = fmaxf(acc[mf][nf][2] + b0, 0.f) * w1;
                float v3 = fmaxf(acc[mf][nf][3] + b1, 0.f) * w1;
                *(__half2*)(d1 + col) = __floats2half2_rn(v2, v3);
            }
        }
    }
}

// ---- combine: fp16 scratch -> fp32 out ------------------------------------------
__global__ void combine_kernel(float* __restrict__ out) {
    size_t i = (size_t)blockIdx.x * blockDim.x + threadIdx.x;   // per 4 elems
    if (i < (size_t)N_TOK * DIM / 4) {
        uint2 p0 = ((const uint2*)g_Ch)[i];
        uint2 p1 = ((const uint2*)(g_Ch + (size_t)N_TOK * DIM))[i];
        float2 a0 = __half22float2(*(__half2*)&p0.x);
        float2 a1 = __half22float2(*(__half2*)&p0.y);
        float2 b0 = __half22float2(*(__half2*)&p1.x);
        float2 b1 = __half22float2(*(__half2*)&p1.y);
        ((float4*)out)[i] = make_float4(a0.x + b0.x, a0.y + b0.y,
                                        a1.x + b1.x, a1.y + b1.y);
    }
}

// ---- launch ----------------------------------------------------------------------
extern "C" void kernel_launch(void* const* d_in, const int* in_sizes, int n_in,
                              void* d_out, int out_size) {
    const float* x  = (const float*)d_in[0];
    const float* We = (const float*)d_in[1];
    const float* be = (const float*)d_in[2];
    const float* Wg = (const float*)d_in[3];
    const float* bg = (const float*)d_in[4];
    float* out = (float*)d_out;

    cudaFuncSetAttribute(expert_gemm_mma,
                         cudaFuncAttributeMaxDynamicSharedMemorySize, SMEM_BYTES);

    reset_kernel<<<1, 32>>>();
    prep_kernel<<<PREP_BLOCKS, 256>>>(x, Wg, bg, We);
    expert_gemm_mma<<<dim3(DIM / BN, N_TOK / BM, NEXP), 512, SMEM_BYTES>>>(be);
    combine_kernel<<<(N_TOK * DIM / 4) / 256, 256>>>(out);
}

// round 14
// speedup vs baseline: 1.3169x; 1.0296x over previous
#include <cuda_runtime.h>
#include <cuda_fp16.h>
#include <cstdint>

#define N_TOK 8192
#define DIM   2048
#define NEXP  8

#define BM 128
#define BN 256
#define BK 64                  // fp16 K elems per chunk (128B row)
#define NCH (DIM / BK)         // 32
#define NSTAGE 3

#define PITCH 144              // 128B data + 16B pad -> conflict-free LDSM
#define A_TILE (BM * PITCH)    // 18432
#define B_TILE (BN * PITCH)    // 36864
#define ST_SIZE (A_TILE + B_TILE)        // 55296
#define OFF_TOK  (NSTAGE * ST_SIZE)      // 165888
#define OFF_WT   (OFF_TOK + 512)
#define OFF_SLOT (OFF_WT + 512)
#define SMEM_BYTES (OFF_SLOT + 512)      // 167424

#define CONV_N4 ((size_t)NEXP * DIM * DIM / 4)   // 8M float4
#define CONV_PER_THREAD 4
#define CONV_THREADS ((size_t)(CONV_N4 / CONV_PER_THREAD))   // 2M
#define CONV_BLOCKS ((int)(CONV_THREADS / 256))              // 8192

// ---- scratch ---------------------------------------------------------------
__device__ int   g_count[NEXP];
__device__ int   g_tok[NEXP][N_TOK];
__device__ float g_wt[NEXP][N_TOK];
__device__ int   g_slot[NEXP][N_TOK];
__device__ __align__(16) __half g_Ch[2ull * N_TOK * DIM];   // fp16 per-slot scratch
__device__ __align__(16) __half g_Wh[(size_t)NEXP * DIM * DIM];
__device__ __align__(16) __half g_Xh[(size_t)N_TOK * DIM];

// ---- helpers -----------------------------------------------------------------
__device__ __forceinline__ uint32_t smem_u32(const void* p) {
    return (uint32_t)__cvta_generic_to_shared(p);
}
__device__ __forceinline__ void cp16(uint32_t dst, const void* src) {
    asm volatile("cp.async.cg.shared.global [%0], [%1], 16;" :: "r"(dst), "l"(src));
}
__device__ __forceinline__ void cp_commit() {
    asm volatile("cp.async.commit_group;" ::: "memory");
}
template <int N>
__device__ __forceinline__ void cp_wait() {
    asm volatile("cp.async.wait_group %0;" :: "n"(N) : "memory");
}
__device__ __forceinline__ void ldsm4(uint32_t& r0, uint32_t& r1, uint32_t& r2,
                                      uint32_t& r3, uint32_t addr) {
    asm volatile("ldmatrix.sync.aligned.m8n8.x4.shared.b16 {%0,%1,%2,%3}, [%4];"
                 : "=r"(r0), "=r"(r1), "=r"(r2), "=r"(r3) : "r"(addr));
}
__device__ __forceinline__ void mma16816(float* c, const uint32_t* a, const uint32_t* b) {
    asm volatile(
        "mma.sync.aligned.m16n8k16.row.col.f32.f16.f16.f32 "
        "{%0,%1,%2,%3}, {%4,%5,%6,%7}, {%8,%9}, {%0,%1,%2,%3};"
        : "+f"(c[0]), "+f"(c[1]), "+f"(c[2]), "+f"(c[3])
        : "r"(a[0]), "r"(a[1]), "r"(a[2]), "r"(a[3]), "r"(b[0]), "r"(b[1]));
}

// ---- W convert (MLP=4) + count reset -------------------------------------------
__global__ void convert_kernel(const float* __restrict__ We) {
    if (blockIdx.x == 0 && threadIdx.x < NEXP) g_count[threadIdx.x] = 0;

    size_t base = (size_t)blockIdx.x * blockDim.x + threadIdx.x;
    const size_t stride = (size_t)gridDim.x * blockDim.x;   // 2M threads
    const float4* src = (const float4*)We;
    uint2* dst = (uint2*)g_Wh;

    // 4 independent loads in flight per thread
    float4 v[CONV_PER_THREAD];
#pragma unroll
    for (int j = 0; j < CONV_PER_THREAD; j++)
        v[j] = __ldg(src + base + j * stride);
#pragma unroll
    for (int j = 0; j < CONV_PER_THREAD; j++) {
        __half2 a = __floats2half2_rn(v[j].x, v[j].y);
        __half2 b = __floats2half2_rn(v[j].z, v[j].w);
        dst[base + j * stride] = make_uint2(*(uint32_t*)&a, *(uint32_t*)&b);
    }
}

// ---- gating: 2 tokens per warp, fused x->fp16 emit (proven 36us) -----------------
__global__ void gating_kernel(const float* __restrict__ x,
                              const float* __restrict__ Wg,
                              const float* __restrict__ bg) {
    int warp = (blockIdx.x * blockDim.x + threadIdx.x) >> 5;
    int lane = threadIdx.x & 31;
    int t0 = warp * 2;
    if (t0 >= N_TOK) return;

    const float4* xr0 = reinterpret_cast<const float4*>(x + (size_t)t0 * DIM);
    const float4* xr1 = reinterpret_cast<const float4*>(x + (size_t)(t0 + 1) * DIM);
    uint2* xh0 = reinterpret_cast<uint2*>(g_Xh + (size_t)t0 * DIM);
    uint2* xh1 = reinterpret_cast<uint2*>(g_Xh + (size_t)(t0 + 1) * DIM);

    float acc0[NEXP], acc1[NEXP];
#pragma unroll
    for (int e = 0; e < NEXP; e++) { acc0[e] = 0.f; acc1[e] = 0.f; }

    for (int d4 = lane; d4 < DIM / 4; d4 += 32) {
        float4 xv0 = __ldg(&xr0[d4]);
        float4 xv1 = __ldg(&xr1[d4]);
        {
            __half2 a0 = __floats2half2_rn(xv0.x, xv0.y);
            __half2 b0 = __floats2half2_rn(xv0.z, xv0.w);
            xh0[d4] = make_uint2(*(uint32_t*)&a0, *(uint32_t*)&b0);
            __half2 a1 = __floats2half2_rn(xv1.x, xv1.y);
            __half2 b1 = __floats2half2_rn(xv1.z, xv1.w);
            xh1[d4] = make_uint2(*(uint32_t*)&a1, *(uint32_t*)&b1);
        }
#pragma unroll
        for (int e = 0; e < NEXP; e++) {
            float4 wv = __ldg(&reinterpret_cast<const float4*>(Wg + (size_t)e * DIM)[d4]);
            acc0[e] += xv0.x * wv.x + xv0.y * wv.y + xv0.z * wv.z + xv0.w * wv.w;
            acc1[e] += xv1.x * wv.x + xv1.y * wv.y + xv1.z * wv.z + xv1.w * wv.w;
        }
    }
#pragma unroll
    for (int e = 0; e < NEXP; e++) {
#pragma unroll
        for (int off = 16; off > 0; off >>= 1) {
            acc0[e] += __shfl_xor_sync(0xffffffffu, acc0[e], off);
            acc1[e] += __shfl_xor_sync(0xffffffffu, acc1[e], off);
        }
    }

    if (lane == 0) {
#pragma unroll
        for (int t = 0; t < 2; t++) {
            float* acc = t ? acc1 : acc0;
            int tok = t0 + t;
            float lg[NEXP];
            float mx = -1e30f;
#pragma unroll
            for (int e = 0; e < NEXP; e++) { lg[e] = acc[e] + bg[e]; mx = fmaxf(mx, lg[e]); }
            float s = 0.f;
#pragma unroll
            for (int e = 0; e < NEXP; e++) { lg[e] = expf(lg[e] - mx); s += lg[e]; }
            float inv = 1.f / s;

            int e0 = 0;
#pragma unroll
            for (int e = 1; e < NEXP; e++) if (lg[e] > lg[e0]) e0 = e;
            int e1 = (e0 == 0) ? 1 : 0;
#pragma unroll
            for (int e = 0; e < NEXP; e++) if (e != e0 && lg[e] > lg[e1]) e1 = e;

            int p0 = atomicAdd(&g_count[e0], 1);
            g_tok[e0][p0] = tok; g_wt[e0][p0] = lg[e0] * inv; g_slot[e0][p0] = 0;
            int p1 = atomicAdd(&g_count[e1], 1);
            g_tok[e1][p1] = tok; g_wt[e1][p1] = lg[e1] * inv; g_slot[e1][p1] = 1;
        }
    }
}

// ---- fp16 mma.sync expert GEMM (unchanged from R13) ------------------------------
__global__ __launch_bounds__(512, 1)
void expert_gemm_mma(const float* __restrict__ be) {
    extern __shared__ __align__(128) char smem[];

    const int e  = blockIdx.z;
    const int Me = g_count[e];
    const int m0 = blockIdx.y * BM;
    if (m0 >= Me) return;
    const int n0 = blockIdx.x * BN;

    const int tid  = threadIdx.x;
    const int wid  = tid >> 5;
    const int lane = tid & 31;

    int*   tok_s  = (int*)(smem + OFF_TOK);
    float* w_s    = (float*)(smem + OFF_WT);
    int*   slot_s = (int*)(smem + OFF_SLOT);

    if (tid < BM) {
        int gm = m0 + tid;
        if (gm < Me) {
            tok_s[tid] = g_tok[e][gm]; w_s[tid] = g_wt[e][gm]; slot_s[tid] = g_slot[e][gm];
        } else {
            tok_s[tid] = 0; w_s[tid] = 0.f; slot_s[tid] = 0;
        }
    }
    __syncthreads();

    const int lr = tid >> 2;        // 0..127
    const int lc = tid & 3;
    const __half* Asrc = g_Xh + (size_t)tok_s[lr] * DIM + lc * 8;
    const __half* Bbase = g_Wh + (size_t)e * DIM * DIM;
    const __half* Bsrc0 = Bbase + (size_t)(n0 + lr) * DIM + lc * 8;
    const __half* Bsrc1 = Bbase + (size_t)(n0 + 128 + lr) * DIM + lc * 8;

    const uint32_t sbase  = smem_u32(smem);
    const uint32_t a_dst  = sbase + lr * PITCH + lc * 16;
    const uint32_t b_dst0 = sbase + A_TILE + lr * PITCH + lc * 16;
    const uint32_t b_dst1 = sbase + A_TILE + (128 + lr) * PITCH + lc * 16;

    const int wm = (wid & 3) * 32;
    const int wn = (wid >> 2) * 64;

    float acc[2][8][4];
#pragma unroll
    for (int mf = 0; mf < 2; mf++)
#pragma unroll
        for (int nf = 0; nf < 8; nf++)
#pragma unroll
            for (int j = 0; j < 4; j++) acc[mf][nf][j] = 0.f;

    const uint32_t aRowAddr = (uint32_t)((wm + (lane & 15)) * PITCH + (lane >> 4) * 16);
    const uint32_t bRowAddr = (uint32_t)((wn + (lane & 7) + ((lane >> 4) << 3)) * PITCH +
                                         ((lane >> 3) & 1) * 16);

    // prologue: chunks 0,1 into stages 0,1
#pragma unroll
    for (int c = 0; c < 2; c++) {
        const uint32_t so = c * ST_SIZE;
        const int k0 = c * BK;
        cp16(a_dst + so,       Asrc + k0);
        cp16(a_dst + so + 64,  Asrc + k0 + 32);
        cp16(b_dst0 + so,      Bsrc0 + k0);
        cp16(b_dst0 + so + 64, Bsrc0 + k0 + 32);
        cp16(b_dst1 + so,      Bsrc1 + k0);
        cp16(b_dst1 + so + 64, Bsrc1 + k0 + 32);
        cp_commit();
    }

    int st = 0;
    for (int c = 0; c < NCH; c++) {
        cp_wait<1>();              // chunk c resident
        __syncthreads();           // stage (c-1)%3 retired by all warps

        const uint32_t bA = sbase + st * ST_SIZE;
        const uint32_t bB = bA + A_TILE;
#pragma unroll
        for (int ks = 0; ks < 4; ks++) {
            const uint32_t kb = ks * 32;
            uint32_t ah[2][4], bb[8][2];
#pragma unroll
            for (int mf = 0; mf < 2; mf++)
                ldsm4(ah[mf][0], ah[mf][1], ah[mf][2], ah[mf][3],
                      bA + aRowAddr + mf * 16 * PITCH + kb);
#pragma unroll
            for (int q = 0; q < 4; q++)
                ldsm4(bb[2 * q][0], bb[2 * q][1], bb[2 * q + 1][0], bb[2 * q + 1][1],
                      bB + bRowAddr + q * 16 * PITCH + kb);
#pragma unroll
            for (int mf = 0; mf < 2; mf++)
#pragma unroll
                for (int nf = 0; nf < 8; nf++)
                    mma16816(acc[mf][nf], ah[mf], bb[nf]);
        }

        // issue chunk c+2 into stage (c+2)%3 == (c-1)%3
        if (c + 2 < NCH) {
            const uint32_t so = ((c + 2) % NSTAGE) * ST_SIZE;
            const int k0 = (c + 2) * BK;
            cp16(a_dst + so,       Asrc + k0);
            cp16(a_dst + so + 64,  Asrc + k0 + 32);
            cp16(b_dst0 + so,      Bsrc0 + k0);
            cp16(b_dst0 + so + 64, Bsrc0 + k0 + 32);
            cp16(b_dst1 + so,      Bsrc1 + k0);
            cp16(b_dst1 + so + 64, Bsrc1 + k0 + 32);
        }
        cp_commit();

        st = (st + 1 == NSTAGE) ? 0 : st + 1;
    }

    // ---- epilogue: bias + relu + gate weight -> g_Ch (fp16, coalesced) -----------
#pragma unroll
    for (int mf = 0; mf < 2; mf++) {
        const int lm0 = wm + mf * 16 + (lane >> 2);
        const int lm1 = lm0 + 8;
        const bool ok0 = (m0 + lm0) < Me;
        const bool ok1 = (m0 + lm1) < Me;
        const float w0 = w_s[lm0], w1 = w_s[lm1];
        __half* d0 = g_Ch + (size_t)slot_s[lm0] * N_TOK * DIM + (size_t)tok_s[lm0] * DIM;
        __half* d1 = g_Ch + (size_t)slot_s[lm1] * N_TOK * DIM + (size_t)tok_s[lm1] * DIM;
#pragma unroll
        for (int nf = 0; nf < 8; nf++) {
            const int col = n0 + wn + nf * 8 + (lane & 3) * 2;
            const float b0 = __ldg(&be[(size_t)e * DIM + col]);
            const float b1 = __ldg(&be[(size_t)e * DIM + col + 1]);
            if (ok0) {
                float v0 = fmaxf(acc[mf][nf][0] + b0, 0.f) * w0;
                float v1 = fmaxf(acc[mf][nf][1] + b1, 0.f) * w0;
                *(__half2*)(d0 + col) = __floats2half2_rn(v0, v1);
            }
            if (ok1) {
                float v2 = fmaxf(acc[mf][nf][2] + b0, 0.f) * w1;
                float v3 = fmaxf(acc[mf][nf][3] + b1, 0.f) * w1;
                *(__half2*)(d1 + col) = __floats2half2_rn(v2, v3);
            }
        }
    }
}

// ---- combine: fp16 scratch -> fp32 out ------------------------------------------
__global__ void combine_kernel(float* __restrict__ out) {
    size_t i = (size_t)blockIdx.x * blockDim.x + threadIdx.x;   // per 4 elems
    if (i < (size_t)N_TOK * DIM / 4) {
        uint2 p0 = ((const uint2*)g_Ch)[i];
        uint2 p1 = ((const uint2*)(g_Ch + (size_t)N_TOK * DIM))[i];
        float2 a0 = __half22float2(*(__half2*)&p0.x);
        float2 a1 = __half22float2(*(__half2*)&p0.y);
        float2 b0 = __half22float2(*(__half2*)&p1.x);
        float2 b1 = __half22float2(*(__half2*)&p1.y);
        ((float4*)out)[i] = make_float4(a0.x + b0.x, a0.y + b0.y,
                                        a1.x + b1.x, a1.y + b1.y);
    }
}

// ---- launch ----------------------------------------------------------------------
extern "C" void kernel_launch(void* const* d_in, const int* in_sizes, int n_in,
                              void* d_out, int out_size) {
    const float* x  = (const float*)d_in[0];
    const float* We = (const float*)d_in[1];
    const float* be = (const float*)d_in[2];
    const float* Wg = (const float*)d_in[3];
    const float* bg = (const float*)d_in[4];
    float* out = (float*)d_out;

    cudaFuncSetAttribute(expert_gemm_mma,
                         cudaFuncAttributeMaxDynamicSharedMemorySize, SMEM_BYTES);

    convert_kernel<<<CONV_BLOCKS, 256>>>(We);            // also resets g_count
    gating_kernel<<<N_TOK / 16, 256>>>(x, Wg, bg);       // also emits g_Xh
    expert_gemm_mma<<<dim3(DIM / BN, N_TOK / BM, NEXP), 512, SMEM_BYTES>>>(be);
    combine_kernel<<<(N_TOK * DIM / 4) / 256, 256>>>(out);
}